// round 2
// baseline (speedup 1.0000x reference)
#include <cuda_runtime.h>

#define B_    1024
#define D_    256
#define V_    256
#define S_    65536
#define NSPLIT 32
#define SPS   (S_/NSPLIT)   /* 2048 slots per split */
#define BM    64
#define BN    64
#define NTILES (SPS/BN)     /* 32 */
#define NREP  1024

/* output layout (floats) */
#define OFF_RETR   0
#define OFF_SUR    (B_*V_)                       /* 262144 */
#define OFF_KEYS   (OFF_SUR + B_)                /* 263168 */
#define OFF_VALS   (OFF_KEYS + S_*D_)            /* 17040384 */
#define OFF_AGE    (OFF_VALS + S_*V_)            /* 33817600 */

/* ---- scratch (no allocs allowed) ---- */
__device__ __align__(16) float g_qn[B_*D_];
__device__ float g_q2[B_];
__device__ float g_k2[S_];
__device__ float g_Opart[(size_t)B_*V_*NSPLIT];  /* 33.5 MB */
__device__ float g_m[B_*NSPLIT];
__device__ float g_l[B_*NSPLIT];
__device__ float g_surprise[B_];
__device__ float g_smean;
__device__ unsigned int g_hist[4096];
__device__ int g_binT;
__device__ int g_ncand;
__device__ unsigned long long g_candkey[S_];
__device__ int g_candidx[S_];
__device__ int g_sel[NREP];

__device__ __forceinline__ unsigned int fkey(float f) {
    unsigned int u = __float_as_uint(f);
    return (u & 0x80000000u) ? ~u : (u | 0x80000000u);
}

/* ---------------- init: zero per-launch scratch ---------------- */
__global__ void init_kernel() {
    int t = threadIdx.x;
    for (int i = t; i < 4096; i += 256) g_hist[i] = 0u;
    if (t == 0) g_ncand = 0;
}

/* ---------------- LayerNorm(query) + q2 ---------------- */
__global__ void ln_kernel(const float* __restrict__ q,
                          const float* __restrict__ gamma,
                          const float* __restrict__ beta) {
    int b = blockIdx.x, t = threadIdx.x;
    __shared__ float red[8];
    __shared__ float bc;
    float x = q[b*D_ + t];

    float s = x;
    #pragma unroll
    for (int o = 16; o; o >>= 1) s += __shfl_xor_sync(0xffffffffu, s, o);
    if ((t & 31) == 0) red[t >> 5] = s;
    __syncthreads();
    if (t == 0) { float v = 0.f; for (int i = 0; i < 8; i++) v += red[i]; bc = v * (1.0f/D_); }
    __syncthreads();
    float mu = bc;
    float d  = x - mu;
    __syncthreads();

    s = d * d;
    #pragma unroll
    for (int o = 16; o; o >>= 1) s += __shfl_xor_sync(0xffffffffu, s, o);
    if ((t & 31) == 0) red[t >> 5] = s;
    __syncthreads();
    if (t == 0) { float v = 0.f; for (int i = 0; i < 8; i++) v += red[i]; bc = v * (1.0f/D_); }
    __syncthreads();
    float var = bc;

    float qn = d * rsqrtf(var + 1e-5f) * gamma[t] + beta[t];
    g_qn[b*D_ + t] = qn;
    __syncthreads();

    s = qn * qn;
    #pragma unroll
    for (int o = 16; o; o >>= 1) s += __shfl_xor_sync(0xffffffffu, s, o);
    if ((t & 31) == 0) red[t >> 5] = s;
    __syncthreads();
    if (t == 0) { float v = 0.f; for (int i = 0; i < 8; i++) v += red[i]; g_q2[b] = v; }
}

/* ---------------- k2 = rowwise ||k||^2 ---------------- */
__global__ void k2_kernel(const float* __restrict__ keys) {
    int row  = blockIdx.x * 8 + (threadIdx.x >> 5);
    int lane = threadIdx.x & 31;
    const float4* K4 = (const float4*)keys;
    float s = 0.f;
    #pragma unroll
    for (int c = lane; c < 64; c += 32) {
        float4 v = K4[(size_t)row*64 + c];
        s += v.x*v.x + v.y*v.y + v.z*v.z + v.w*v.w;
    }
    #pragma unroll
    for (int o = 16; o; o >>= 1) s += __shfl_xor_sync(0xffffffffu, s, o);
    if (lane == 0) g_k2[row] = s;
}

/* ---------------- fused flash attention (split-S partials) ---------------- */
__global__ void __launch_bounds__(256, 1)
flash_kernel(const float* __restrict__ keys, const float* __restrict__ values) {
    extern __shared__ char smem_raw[];
    float4* sQ  = (float4*)smem_raw;          /* 64 x 65 float4 */
    float4* sK  = sQ + 64*65;
    float4* sV  = sK + 64*65;
    float*  sS  = (float*)(sV + 64*65);       /* 64 x 65 floats */
    float*  sq2 = sS + 64*65;
    float*  sk2 = sq2 + 64;
    float*  sM  = sk2 + 64;
    float*  sL  = sM + 64;
    float*  sAl = sL + 64;

    const int qb = blockIdx.x;   /* 0..15 */
    const int sp = blockIdx.y;   /* 0..31 */
    const int tid = threadIdx.x;
    const int m0 = qb * BM;
    const int ty = tid >> 4, tx = tid & 15;

    const float4* Q4 = (const float4*)g_qn;
    for (int idx = tid; idx < 64*64; idx += 256) {
        int r = idx >> 6, c = idx & 63;
        sQ[r*65 + c] = Q4[(size_t)(m0 + r)*64 + c];
    }
    if (tid < 64) { sq2[tid] = g_q2[m0 + tid]; sM[tid] = -1e30f; sL[tid] = 0.f; }

    float Oacc[4][16];
    #pragma unroll
    for (int i = 0; i < 4; i++)
        #pragma unroll
        for (int c = 0; c < 16; c++) Oacc[i][c] = 0.f;

    const float4* K4 = (const float4*)keys;
    const float4* V4 = (const float4*)values;

    for (int tI = 0; tI < NTILES; tI++) {
        int s0 = sp * SPS + tI * BN;
        __syncthreads();  /* prev PV done */
        for (int idx = tid; idx < 64*64; idx += 256) {
            int r = idx >> 6, c = idx & 63;
            sK[r*65 + c] = K4[(size_t)(s0 + r)*64 + c];
            sV[r*65 + c] = V4[(size_t)(s0 + r)*64 + c];
        }
        if (tid < 64) sk2[tid] = g_k2[s0 + tid];
        __syncthreads();

        /* ---- QK: 4x4 per thread ---- */
        float acc[4][4];
        #pragma unroll
        for (int i = 0; i < 4; i++)
            #pragma unroll
            for (int j = 0; j < 4; j++) acc[i][j] = 0.f;

        #pragma unroll 2
        for (int d = 0; d < 64; d++) {
            float4 qv[4], kv[4];
            #pragma unroll
            for (int i = 0; i < 4; i++) qv[i] = sQ[(ty*4 + i)*65 + d];
            #pragma unroll
            for (int j = 0; j < 4; j++) kv[j] = sK[(tx*4 + j)*65 + d];
            #pragma unroll
            for (int i = 0; i < 4; i++)
                #pragma unroll
                for (int j = 0; j < 4; j++)
                    acc[i][j] += qv[i].x*kv[j].x + qv[i].y*kv[j].y
                               + qv[i].z*kv[j].z + qv[i].w*kv[j].w;
        }
        #pragma unroll
        for (int i = 0; i < 4; i++) {
            int r = ty*4 + i;
            #pragma unroll
            for (int j = 0; j < 4; j++) {
                int c = tx*4 + j;
                float d2 = fmaxf(sq2[r] + sk2[c] - 2.0f*acc[i][j], 0.0f);
                sS[r*65 + c] = -d2;   /* TEMPERATURE = 1 */
            }
        }
        __syncthreads();

        /* ---- online softmax: 4 threads per row ---- */
        {
            int r = tid >> 2, g = tid & 3;
            float mloc = -1e30f;
            #pragma unroll
            for (int k = 0; k < 16; k++) mloc = fmaxf(mloc, sS[r*65 + g*16 + k]);
            mloc = fmaxf(mloc, __shfl_xor_sync(0xffffffffu, mloc, 1));
            mloc = fmaxf(mloc, __shfl_xor_sync(0xffffffffu, mloc, 2));
            float mold = sM[r];
            float mnew = fmaxf(mold, mloc);
            float psum = 0.f;
            #pragma unroll
            for (int k = 0; k < 16; k++) {
                float p = __expf(sS[r*65 + g*16 + k] - mnew);
                sS[r*65 + g*16 + k] = p;
                psum += p;
            }
            psum += __shfl_xor_sync(0xffffffffu, psum, 1);
            psum += __shfl_xor_sync(0xffffffffu, psum, 2);
            if (g == 0) {
                float al = __expf(mold - mnew);
                sAl[r] = al; sM[r] = mnew; sL[r] = sL[r]*al + psum;
            }
        }
        __syncthreads();

        /* ---- rescale + PV: 4 rows x 16 cols per thread ---- */
        #pragma unroll
        for (int i = 0; i < 4; i++) {
            float al = sAl[ty*4 + i];
            #pragma unroll
            for (int c = 0; c < 16; c++) Oacc[i][c] *= al;
        }
        for (int s = 0; s < 64; s++) {
            float p[4];
            #pragma unroll
            for (int i = 0; i < 4; i++) p[i] = sS[(ty*4 + i)*65 + s];
            float4 v0 = sV[s*65 + tx*4 + 0];
            float4 v1 = sV[s*65 + tx*4 + 1];
            float4 v2 = sV[s*65 + tx*4 + 2];
            float4 v3 = sV[s*65 + tx*4 + 3];
            #pragma unroll
            for (int i = 0; i < 4; i++) {
                Oacc[i][0]  += p[i]*v0.x; Oacc[i][1]  += p[i]*v0.y;
                Oacc[i][2]  += p[i]*v0.z; Oacc[i][3]  += p[i]*v0.w;
                Oacc[i][4]  += p[i]*v1.x; Oacc[i][5]  += p[i]*v1.y;
                Oacc[i][6]  += p[i]*v1.z; Oacc[i][7]  += p[i]*v1.w;
                Oacc[i][8]  += p[i]*v2.x; Oacc[i][9]  += p[i]*v2.y;
                Oacc[i][10] += p[i]*v2.z; Oacc[i][11] += p[i]*v2.w;
                Oacc[i][12] += p[i]*v3.x; Oacc[i][13] += p[i]*v3.y;
                Oacc[i][14] += p[i]*v3.z; Oacc[i][15] += p[i]*v3.w;
            }
        }
    }

    /* ---- write partials ---- */
    size_t base = (size_t)(qb*NSPLIT + sp) * BM * V_;
    #pragma unroll
    for (int i = 0; i < 4; i++)
        #pragma unroll
        for (int c = 0; c < 16; c++)
            g_Opart[base + (size_t)(ty*4 + i)*V_ + tx*16 + c] = Oacc[i][c];
    if (tid < 64) {
        g_m[(m0 + tid)*NSPLIT + sp] = sM[tid];
        g_l[(m0 + tid)*NSPLIT + sp] = sL[tid];
    }
}

/* ---------------- combine splits -> retrieved + surprise ---------------- */
__global__ void combine_kernel(const float* __restrict__ vt, float* __restrict__ out) {
    int b = blockIdx.x, t = threadIdx.x;
    int qb = b >> 6, rl = b & 63;
    float M = -1e30f;
    #pragma unroll
    for (int i = 0; i < NSPLIT; i++) M = fmaxf(M, g_m[b*NSPLIT + i]);
    float w[NSPLIT];
    float L = 0.f;
    #pragma unroll
    for (int i = 0; i < NSPLIT; i++) {
        w[i] = __expf(g_m[b*NSPLIT + i] - M);
        L += g_l[b*NSPLIT + i] * w[i];
    }
    float acc = 0.f;
    #pragma unroll
    for (int i = 0; i < NSPLIT; i++)
        acc += w[i] * g_Opart[((size_t)(qb*NSPLIT + i)*BM + rl)*V_ + t];
    float r = acc / L;
    out[OFF_RETR + (size_t)b*V_ + t] = r;

    float e = r - vt[(size_t)b*V_ + t];
    float s = e * e;
    __shared__ float red[8];
    #pragma unroll
    for (int o = 16; o; o >>= 1) s += __shfl_xor_sync(0xffffffffu, s, o);
    if ((t & 31) == 0) red[t >> 5] = s;
    __syncthreads();
    if (t == 0) {
        float v = 0.f;
        for (int i = 0; i < 8; i++) v += red[i];
        float sur = v * (1.0f/V_);
        out[OFF_SUR + b] = sur;
        g_surprise[b] = sur;
    }
}

/* ---------------- mean(surprise), deterministic ---------------- */
__global__ void mean_kernel() {
    int t = threadIdx.x;
    __shared__ float red[8];
    float s = 0.f;
    for (int i = t; i < B_; i += 256) s += g_surprise[i];
    #pragma unroll
    for (int o = 16; o; o >>= 1) s += __shfl_xor_sync(0xffffffffu, s, o);
    if ((t & 31) == 0) red[t >> 5] = s;
    __syncthreads();
    if (t == 0) {
        float v = 0.f;
        for (int i = 0; i < 8; i++) v += red[i];
        g_smean = v * (1.0f/B_);
    }
}

/* ---------------- top-k selection (general, value-desc, index-stable) ---------------- */
__global__ void hist_kernel(const float* __restrict__ age) {
    int i = blockIdx.x * 256 + threadIdx.x;
    unsigned int u = fkey(age[i]);
    atomicAdd(&g_hist[u >> 20], 1u);
}

__global__ void thresh_kernel() {
    int cum = 0, T = 0;
    for (int i = 4095; i >= 0; i--) {
        cum += (int)g_hist[i];
        if (cum >= NREP) { T = i; break; }
    }
    g_binT = T;
}

__global__ void cand_kernel(const float* __restrict__ age) {
    int i = blockIdx.x * 256 + threadIdx.x;
    unsigned int u = fkey(age[i]);
    if ((int)(u >> 20) >= g_binT) {
        int pos = atomicAdd(&g_ncand, 1);
        g_candkey[pos] = ((unsigned long long)u << 32) | (unsigned int)(~(unsigned int)i);
        g_candidx[pos] = i;
    }
}

__global__ void rank_kernel() {
    int n = g_ncand;
    __shared__ int sr[8];
    for (int c = blockIdx.x; c < n; c += gridDim.x) {
        unsigned long long kk = g_candkey[c];
        int cnt = 0;
        for (int j = threadIdx.x; j < n; j += 256) cnt += (g_candkey[j] > kk) ? 1 : 0;
        #pragma unroll
        for (int o = 16; o; o >>= 1) cnt += __shfl_xor_sync(0xffffffffu, cnt, o);
        if ((threadIdx.x & 31) == 0) sr[threadIdx.x >> 5] = cnt;
        __syncthreads();
        if (threadIdx.x == 0) {
            int tot = 0;
            for (int i = 0; i < 8; i++) tot += sr[i];
            if (tot < NREP) g_sel[tot] = g_candidx[c];
        }
        __syncthreads();
    }
}

/* ---------------- bulk copy keys/values, age+1 ---------------- */
__global__ void copy_kernel(const float* __restrict__ keys, const float* __restrict__ values,
                            const float* __restrict__ age, float* __restrict__ out) {
    size_t gtid = (size_t)blockIdx.x * blockDim.x + threadIdx.x;
    size_t gstr = (size_t)gridDim.x * blockDim.x;
    const float4* K4 = (const float4*)keys;
    const float4* V4 = (const float4*)values;
    float4* oK = (float4*)(out + OFF_KEYS);
    float4* oV = (float4*)(out + OFF_VALS);
    const size_t n4 = (size_t)S_*D_/4;  /* 4194304 */
    for (size_t i = gtid; i < 2*n4; i += gstr) {
        if (i < n4) oK[i] = K4[i];
        else        oV[i - n4] = V4[i - n4];
    }
    for (size_t i = gtid; i < S_; i += gstr)
        out[OFF_AGE + i] = age[i] + 1.0f;
}

/* ---------------- surprise-gated EMA scatter ---------------- */
__global__ void scatter_kernel(const float* __restrict__ keys, const float* __restrict__ values,
                               const float* __restrict__ vt, float* __restrict__ out) {
    int b = blockIdx.x, t = threadIdx.x;
    int slot = g_sel[b];
    float w = 1.0f / (1.0f + __expf(-(g_surprise[b] - g_smean)));
    float decay = 0.99f * (1.0f - w);
    float om = 1.0f - decay;
    out[OFF_KEYS + (size_t)slot*D_ + t] =
        decay * keys[(size_t)slot*D_ + t] + om * g_qn[(size_t)b*D_ + t];
    out[OFF_VALS + (size_t)slot*V_ + t] =
        decay * values[(size_t)slot*V_ + t] + om * vt[(size_t)b*V_ + t];
    if (t == 0) out[OFF_AGE + slot] = 1.0f;
}

/* ---------------- launch ---------------- */
#define SMEM_BYTES (3*64*65*16 + 64*65*4 + 5*64*4)   /* 217600 */

extern "C" void kernel_launch(void* const* d_in, const int* in_sizes, int n_in,
                              void* d_out, int out_size) {
    const float* query  = (const float*)d_in[0];
    const float* vt     = (const float*)d_in[1];
    const float* keys   = (const float*)d_in[2];
    const float* values = (const float*)d_in[3];
    const float* age    = (const float*)d_in[4];
    const float* gamma  = (const float*)d_in[5];
    const float* beta   = (const float*)d_in[6];
    float* out = (float*)d_out;

    cudaFuncSetAttribute(flash_kernel, cudaFuncAttributeMaxDynamicSharedMemorySize, SMEM_BYTES);

    init_kernel<<<1, 256>>>();
    ln_kernel<<<B_, 256>>>(query, gamma, beta);
    k2_kernel<<<S_/8, 256>>>(keys);
    flash_kernel<<<dim3(B_/BM, NSPLIT), 256, SMEM_BYTES>>>(keys, values);
    combine_kernel<<<B_, 256>>>(vt, out);
    mean_kernel<<<1, 256>>>();
    hist_kernel<<<S_/256, 256>>>(age);
    thresh_kernel<<<1, 1>>>();
    cand_kernel<<<S_/256, 256>>>(age);
    rank_kernel<<<256, 256>>>();
    copy_kernel<<<1024, 256>>>(keys, values, age, out);
    scatter_kernel<<<B_, 256>>>(keys, values, vt, out);
}

// round 3
// speedup vs baseline: 1.0009x; 1.0009x over previous
#include <cuda_runtime.h>

#define B_    1024
#define D_    256
#define V_    256
#define S_    65536
#define NSPLIT 32
#define SPS   (S_/NSPLIT)   /* 2048 slots per split */
#define BM    64
#define BN    64
#define NTILES (SPS/BN)     /* 32 */
#define NREP  1024

/* output layout (floats) */
#define OFF_RETR   0
#define OFF_SUR    (B_*V_)                       /* 262144 */
#define OFF_KEYS   (OFF_SUR + B_)                /* 263168 */
#define OFF_VALS   (OFF_KEYS + S_*D_)            /* 17040384 */
#define OFF_AGE    (OFF_VALS + S_*V_)            /* 33817600 */

/* ---- scratch (no allocs allowed) ---- */
__device__ __align__(16) float g_qn[B_*D_];
__device__ float g_q2[B_];
__device__ float g_k2[S_];
__device__ float g_Opart[(size_t)B_*V_*NSPLIT];  /* 33.5 MB */
__device__ float g_m[B_*NSPLIT];
__device__ float g_l[B_*NSPLIT];
__device__ float g_surprise[B_];
__device__ float g_smean;
__device__ unsigned int g_hist[4096];
__device__ int g_binT;
__device__ int g_ncand;
__device__ unsigned long long g_candkey[S_];
__device__ int g_candidx[S_];
__device__ int g_sel[NREP];

__device__ __forceinline__ unsigned int fkey(float f) {
    unsigned int u = __float_as_uint(f);
    return (u & 0x80000000u) ? ~u : (u | 0x80000000u);
}

/* ---------------- init: zero per-launch scratch ---------------- */
__global__ void init_kernel() {
    int t = threadIdx.x;
    for (int i = t; i < 4096; i += 256) g_hist[i] = 0u;
    if (t == 0) g_ncand = 0;
}

/* ---------------- LayerNorm(query) + q2 ---------------- */
__global__ void ln_kernel(const float* __restrict__ q,
                          const float* __restrict__ gamma,
                          const float* __restrict__ beta) {
    int b = blockIdx.x, t = threadIdx.x;
    __shared__ float red[8];
    __shared__ float bc;
    float x = q[b*D_ + t];

    float s = x;
    #pragma unroll
    for (int o = 16; o; o >>= 1) s += __shfl_xor_sync(0xffffffffu, s, o);
    if ((t & 31) == 0) red[t >> 5] = s;
    __syncthreads();
    if (t == 0) { float v = 0.f; for (int i = 0; i < 8; i++) v += red[i]; bc = v * (1.0f/D_); }
    __syncthreads();
    float mu = bc;
    float d  = x - mu;
    __syncthreads();

    s = d * d;
    #pragma unroll
    for (int o = 16; o; o >>= 1) s += __shfl_xor_sync(0xffffffffu, s, o);
    if ((t & 31) == 0) red[t >> 5] = s;
    __syncthreads();
    if (t == 0) { float v = 0.f; for (int i = 0; i < 8; i++) v += red[i]; bc = v * (1.0f/D_); }
    __syncthreads();
    float var = bc;

    float qn = d * rsqrtf(var + 1e-5f) * gamma[t] + beta[t];
    g_qn[b*D_ + t] = qn;
    __syncthreads();

    s = qn * qn;
    #pragma unroll
    for (int o = 16; o; o >>= 1) s += __shfl_xor_sync(0xffffffffu, s, o);
    if ((t & 31) == 0) red[t >> 5] = s;
    __syncthreads();
    if (t == 0) { float v = 0.f; for (int i = 0; i < 8; i++) v += red[i]; g_q2[b] = v; }
}

/* ---------------- k2 = rowwise ||k||^2 ---------------- */
__global__ void k2_kernel(const float* __restrict__ keys) {
    int row  = blockIdx.x * 8 + (threadIdx.x >> 5);
    int lane = threadIdx.x & 31;
    const float4* K4 = (const float4*)keys;
    float s = 0.f;
    #pragma unroll
    for (int c = lane; c < 64; c += 32) {
        float4 v = K4[(size_t)row*64 + c];
        s += v.x*v.x + v.y*v.y + v.z*v.z + v.w*v.w;
    }
    #pragma unroll
    for (int o = 16; o; o >>= 1) s += __shfl_xor_sync(0xffffffffu, s, o);
    if (lane == 0) g_k2[row] = s;
}

/* ---------------- fused flash attention (split-S partials) ---------------- */
__global__ void __launch_bounds__(256, 1)
flash_kernel(const float* __restrict__ keys, const float* __restrict__ values) {
    extern __shared__ char smem_raw[];
    float4* sQ  = (float4*)smem_raw;          /* 64 x 65 float4 */
    float4* sK  = sQ + 64*65;
    float4* sV  = sK + 64*65;
    float*  sS  = (float*)(sV + 64*65);       /* 64 x 65 floats */
    float*  sq2 = sS + 64*65;
    float*  sk2 = sq2 + 64;
    float*  sM  = sk2 + 64;
    float*  sL  = sM + 64;
    float*  sAl = sL + 64;

    const int qb = blockIdx.x;   /* 0..15 */
    const int sp = blockIdx.y;   /* 0..31 */
    const int tid = threadIdx.x;
    const int m0 = qb * BM;
    const int ty = tid >> 4, tx = tid & 15;

    const float4* Q4 = (const float4*)g_qn;
    for (int idx = tid; idx < 64*64; idx += 256) {
        int r = idx >> 6, c = idx & 63;
        sQ[r*65 + c] = Q4[(size_t)(m0 + r)*64 + c];
    }
    if (tid < 64) { sq2[tid] = g_q2[m0 + tid]; sM[tid] = -1e30f; sL[tid] = 0.f; }

    float Oacc[4][16];
    #pragma unroll
    for (int i = 0; i < 4; i++)
        #pragma unroll
        for (int c = 0; c < 16; c++) Oacc[i][c] = 0.f;

    const float4* K4 = (const float4*)keys;
    const float4* V4 = (const float4*)values;

    for (int tI = 0; tI < NTILES; tI++) {
        int s0 = sp * SPS + tI * BN;
        __syncthreads();  /* prev PV done */
        for (int idx = tid; idx < 64*64; idx += 256) {
            int r = idx >> 6, c = idx & 63;
            sK[r*65 + c] = K4[(size_t)(s0 + r)*64 + c];
            sV[r*65 + c] = V4[(size_t)(s0 + r)*64 + c];
        }
        if (tid < 64) sk2[tid] = g_k2[s0 + tid];
        __syncthreads();

        /* ---- QK: 4x4 per thread ---- */
        float acc[4][4];
        #pragma unroll
        for (int i = 0; i < 4; i++)
            #pragma unroll
            for (int j = 0; j < 4; j++) acc[i][j] = 0.f;

        #pragma unroll 2
        for (int d = 0; d < 64; d++) {
            float4 qv[4], kv[4];
            #pragma unroll
            for (int i = 0; i < 4; i++) qv[i] = sQ[(ty*4 + i)*65 + d];
            #pragma unroll
            for (int j = 0; j < 4; j++) kv[j] = sK[(tx*4 + j)*65 + d];
            #pragma unroll
            for (int i = 0; i < 4; i++)
                #pragma unroll
                for (int j = 0; j < 4; j++)
                    acc[i][j] += qv[i].x*kv[j].x + qv[i].y*kv[j].y
                               + qv[i].z*kv[j].z + qv[i].w*kv[j].w;
        }
        #pragma unroll
        for (int i = 0; i < 4; i++) {
            int r = ty*4 + i;
            #pragma unroll
            for (int j = 0; j < 4; j++) {
                int c = tx*4 + j;
                float d2 = fmaxf(sq2[r] + sk2[c] - 2.0f*acc[i][j], 0.0f);
                sS[r*65 + c] = -d2;   /* TEMPERATURE = 1 */
            }
        }
        __syncthreads();

        /* ---- online softmax: 4 threads per row ---- */
        {
            int r = tid >> 2, g = tid & 3;
            float mloc = -1e30f;
            #pragma unroll
            for (int k = 0; k < 16; k++) mloc = fmaxf(mloc, sS[r*65 + g*16 + k]);
            mloc = fmaxf(mloc, __shfl_xor_sync(0xffffffffu, mloc, 1));
            mloc = fmaxf(mloc, __shfl_xor_sync(0xffffffffu, mloc, 2));
            float mold = sM[r];
            float mnew = fmaxf(mold, mloc);
            float psum = 0.f;
            #pragma unroll
            for (int k = 0; k < 16; k++) {
                float p = __expf(sS[r*65 + g*16 + k] - mnew);
                sS[r*65 + g*16 + k] = p;
                psum += p;
            }
            psum += __shfl_xor_sync(0xffffffffu, psum, 1);
            psum += __shfl_xor_sync(0xffffffffu, psum, 2);
            if (g == 0) {
                float al = __expf(mold - mnew);
                sAl[r] = al; sM[r] = mnew; sL[r] = sL[r]*al + psum;
            }
        }
        __syncthreads();

        /* ---- rescale + PV: 4 rows x 16 cols per thread ---- */
        #pragma unroll
        for (int i = 0; i < 4; i++) {
            float al = sAl[ty*4 + i];
            #pragma unroll
            for (int c = 0; c < 16; c++) Oacc[i][c] *= al;
        }
        for (int s = 0; s < 64; s++) {
            float p[4];
            #pragma unroll
            for (int i = 0; i < 4; i++) p[i] = sS[(ty*4 + i)*65 + s];
            float4 v0 = sV[s*65 + tx*4 + 0];
            float4 v1 = sV[s*65 + tx*4 + 1];
            float4 v2 = sV[s*65 + tx*4 + 2];
            float4 v3 = sV[s*65 + tx*4 + 3];
            #pragma unroll
            for (int i = 0; i < 4; i++) {
                Oacc[i][0]  += p[i]*v0.x; Oacc[i][1]  += p[i]*v0.y;
                Oacc[i][2]  += p[i]*v0.z; Oacc[i][3]  += p[i]*v0.w;
                Oacc[i][4]  += p[i]*v1.x; Oacc[i][5]  += p[i]*v1.y;
                Oacc[i][6]  += p[i]*v1.z; Oacc[i][7]  += p[i]*v1.w;
                Oacc[i][8]  += p[i]*v2.x; Oacc[i][9]  += p[i]*v2.y;
                Oacc[i][10] += p[i]*v2.z; Oacc[i][11] += p[i]*v2.w;
                Oacc[i][12] += p[i]*v3.x; Oacc[i][13] += p[i]*v3.y;
                Oacc[i][14] += p[i]*v3.z; Oacc[i][15] += p[i]*v3.w;
            }
        }
    }

    /* ---- write partials ---- */
    size_t base = (size_t)(qb*NSPLIT + sp) * BM * V_;
    #pragma unroll
    for (int i = 0; i < 4; i++)
        #pragma unroll
        for (int c = 0; c < 16; c++)
            g_Opart[base + (size_t)(ty*4 + i)*V_ + tx*16 + c] = Oacc[i][c];
    if (tid < 64) {
        g_m[(m0 + tid)*NSPLIT + sp] = sM[tid];
        g_l[(m0 + tid)*NSPLIT + sp] = sL[tid];
    }
}

/* ---------------- combine splits -> retrieved + surprise ---------------- */
__global__ void combine_kernel(const float* __restrict__ vt, float* __restrict__ out) {
    int b = blockIdx.x, t = threadIdx.x;
    int qb = b >> 6, rl = b & 63;
    float M = -1e30f;
    #pragma unroll
    for (int i = 0; i < NSPLIT; i++) M = fmaxf(M, g_m[b*NSPLIT + i]);
    float w[NSPLIT];
    float L = 0.f;
    #pragma unroll
    for (int i = 0; i < NSPLIT; i++) {
        w[i] = __expf(g_m[b*NSPLIT + i] - M);
        L += g_l[b*NSPLIT + i] * w[i];
    }
    float acc = 0.f;
    #pragma unroll
    for (int i = 0; i < NSPLIT; i++)
        acc += w[i] * g_Opart[((size_t)(qb*NSPLIT + i)*BM + rl)*V_ + t];
    float r = acc / L;
    out[OFF_RETR + (size_t)b*V_ + t] = r;

    float e = r - vt[(size_t)b*V_ + t];
    float s = e * e;
    __shared__ float red[8];
    #pragma unroll
    for (int o = 16; o; o >>= 1) s += __shfl_xor_sync(0xffffffffu, s, o);
    if ((t & 31) == 0) red[t >> 5] = s;
    __syncthreads();
    if (t == 0) {
        float v = 0.f;
        for (int i = 0; i < 8; i++) v += red[i];
        float sur = v * (1.0f/V_);
        out[OFF_SUR + b] = sur;
        g_surprise[b] = sur;
    }
}

/* ---------------- mean(surprise), deterministic ---------------- */
__global__ void mean_kernel() {
    int t = threadIdx.x;
    __shared__ float red[8];
    float s = 0.f;
    for (int i = t; i < B_; i += 256) s += g_surprise[i];
    #pragma unroll
    for (int o = 16; o; o >>= 1) s += __shfl_xor_sync(0xffffffffu, s, o);
    if ((t & 31) == 0) red[t >> 5] = s;
    __syncthreads();
    if (t == 0) {
        float v = 0.f;
        for (int i = 0; i < 8; i++) v += red[i];
        g_smean = v * (1.0f/B_);
    }
}

/* ---------------- top-k selection (general, value-desc, index-stable) ---------------- */
__global__ void hist_kernel(const float* __restrict__ age) {
    int i = blockIdx.x * 256 + threadIdx.x;
    unsigned int u = fkey(age[i]);
    atomicAdd(&g_hist[u >> 20], 1u);
}

__global__ void thresh_kernel() {
    int cum = 0, T = 0;
    for (int i = 4095; i >= 0; i--) {
        cum += (int)g_hist[i];
        if (cum >= NREP) { T = i; break; }
    }
    g_binT = T;
}

__global__ void cand_kernel(const float* __restrict__ age) {
    int i = blockIdx.x * 256 + threadIdx.x;
    unsigned int u = fkey(age[i]);
    if ((int)(u >> 20) >= g_binT) {
        int pos = atomicAdd(&g_ncand, 1);
        g_candkey[pos] = ((unsigned long long)u << 32) | (unsigned int)(~(unsigned int)i);
        g_candidx[pos] = i;
    }
}

__global__ void rank_kernel() {
    int n = g_ncand;
    __shared__ int sr[8];
    for (int c = blockIdx.x; c < n; c += gridDim.x) {
        unsigned long long kk = g_candkey[c];
        int cnt = 0;
        for (int j = threadIdx.x; j < n; j += 256) cnt += (g_candkey[j] > kk) ? 1 : 0;
        #pragma unroll
        for (int o = 16; o; o >>= 1) cnt += __shfl_xor_sync(0xffffffffu, cnt, o);
        if ((threadIdx.x & 31) == 0) sr[threadIdx.x >> 5] = cnt;
        __syncthreads();
        if (threadIdx.x == 0) {
            int tot = 0;
            for (int i = 0; i < 8; i++) tot += sr[i];
            if (tot < NREP) g_sel[tot] = g_candidx[c];
        }
        __syncthreads();
    }
}

/* ---------------- bulk copy keys/values, age+1 ---------------- */
__global__ void copy_kernel(const float* __restrict__ keys, const float* __restrict__ values,
                            const float* __restrict__ age, float* __restrict__ out) {
    size_t gtid = (size_t)blockIdx.x * blockDim.x + threadIdx.x;
    size_t gstr = (size_t)gridDim.x * blockDim.x;
    const float4* K4 = (const float4*)keys;
    const float4* V4 = (const float4*)values;
    float4* oK = (float4*)(out + OFF_KEYS);
    float4* oV = (float4*)(out + OFF_VALS);
    const size_t n4 = (size_t)S_*D_/4;  /* 4194304 */
    for (size_t i = gtid; i < 2*n4; i += gstr) {
        if (i < n4) oK[i] = K4[i];
        else        oV[i - n4] = V4[i - n4];
    }
    for (size_t i = gtid; i < S_; i += gstr)
        out[OFF_AGE + i] = age[i] + 1.0f;
}

/* ---------------- surprise-gated EMA scatter ---------------- */
__global__ void scatter_kernel(const float* __restrict__ keys, const float* __restrict__ values,
                               const float* __restrict__ vt, float* __restrict__ out) {
    int b = blockIdx.x, t = threadIdx.x;
    int slot = g_sel[b];
    float w = 1.0f / (1.0f + __expf(-(g_surprise[b] - g_smean)));
    float decay = 0.99f * (1.0f - w);
    float om = 1.0f - decay;
    out[OFF_KEYS + (size_t)slot*D_ + t] =
        decay * keys[(size_t)slot*D_ + t] + om * g_qn[(size_t)b*D_ + t];
    out[OFF_VALS + (size_t)slot*V_ + t] =
        decay * values[(size_t)slot*V_ + t] + om * vt[(size_t)b*V_ + t];
    if (t == 0) out[OFF_AGE + slot] = 1.0f;
}

/* ---------------- launch ---------------- */
#define SMEM_BYTES (3*64*65*16 + 64*65*4 + 5*64*4)   /* 217600 */

extern "C" void kernel_launch(void* const* d_in, const int* in_sizes, int n_in,
                              void* d_out, int out_size) {
    const float* query  = (const float*)d_in[0];
    const float* vt     = (const float*)d_in[1];
    const float* keys   = (const float*)d_in[2];
    const float* values = (const float*)d_in[3];
    const float* age    = (const float*)d_in[4];
    const float* gamma  = (const float*)d_in[5];
    const float* beta   = (const float*)d_in[6];
    float* out = (float*)d_out;

    cudaFuncSetAttribute(flash_kernel, cudaFuncAttributeMaxDynamicSharedMemorySize, SMEM_BYTES);

    init_kernel<<<1, 256>>>();
    ln_kernel<<<B_, 256>>>(query, gamma, beta);
    k2_kernel<<<S_/8, 256>>>(keys);
    flash_kernel<<<dim3(B_/BM, NSPLIT), 256, SMEM_BYTES>>>(keys, values);
    combine_kernel<<<B_, 256>>>(vt, out);
    mean_kernel<<<1, 256>>>();
    hist_kernel<<<S_/256, 256>>>(age);
    thresh_kernel<<<1, 1>>>();
    cand_kernel<<<S_/256, 256>>>(age);
    rank_kernel<<<256, 256>>>();
    copy_kernel<<<1024, 256>>>(keys, values, age, out);
    scatter_kernel<<<B_, 256>>>(keys, values, vt, out);
}

// round 8
// speedup vs baseline: 5.1302x; 5.1256x over previous
#include <cuda_runtime.h>
#include <cuda_bf16.h>
#include <cstdint>

#define B_    1024
#define D_    256
#define V_    256
#define S_    65536
#define NSPLIT 32
#define NREP  1024

/* output layout (floats) */
#define OFF_RETR   0
#define OFF_SUR    (B_*V_)
#define OFF_KEYS   (OFF_SUR + B_)
#define OFF_VALS   (OFF_KEYS + S_*D_)
#define OFF_AGE    (OFF_VALS + S_*V_)

/* ============ scratch (no allocs allowed) ============ */
__device__ __align__(16) float g_qn[B_*D_];
__device__ float g_q2[B_];
__device__ float g_k2[S_];
__device__ __align__(16) float g_S[(size_t)B_*S_];      /* 268MB tiled: [qb8][tile1024][row128][col64] */
__device__ __align__(16) unsigned short g_Kh[(size_t)S_*D_];  /* bf16 hi, [slot][d] */
__device__ __align__(16) unsigned short g_Kl[(size_t)S_*D_];
__device__ __align__(16) unsigned short g_Vth[(size_t)S_*V_]; /* bf16 hi, per-tile [v256][slot64] */
__device__ __align__(16) unsigned short g_Vtl[(size_t)S_*V_];
__device__ __align__(16) float g_Opart[(size_t)B_*NSPLIT*V_]; /* [m1024][sp32][v256] 33.5MB */
__device__ float g_lpart[B_*NSPLIT];
__device__ unsigned int g_rowmax[B_];
__device__ float g_surprise[B_];
__device__ float g_smean;
__device__ unsigned int g_hist[4096];
__device__ int g_binT;
__device__ int g_ncand;
__device__ unsigned long long g_candkey[S_];
__device__ int g_candidx[S_];
__device__ int g_sel[NREP];

/* ============ helpers ============ */
__device__ __forceinline__ unsigned int fkey(float f) {
    unsigned int u = __float_as_uint(f);
    return (u & 0x80000000u) ? ~u : (u | 0x80000000u);
}
__device__ __forceinline__ float unfkey(unsigned int e) {
    return (e & 0x80000000u) ? __uint_as_float(e & 0x7fffffffu) : __uint_as_float(~e);
}
__device__ __forceinline__ uint32_t smem_u32(const void* p) {
    uint32_t a;
    asm("{ .reg .u64 t; cvta.to.shared.u64 t, %1; cvt.u32.u64 %0, t; }" : "=r"(a) : "l"(p));
    return a;
}
__device__ __forceinline__ void split2(float x0, float x1, uint32_t& h, uint32_t& l) {
    __nv_bfloat16 h0 = __float2bfloat16(x0), h1 = __float2bfloat16(x1);
    float r0 = x0 - __bfloat162float(h0), r1 = x1 - __bfloat162float(h1);
    __nv_bfloat162 hh = __halves2bfloat162(h0, h1);
    __nv_bfloat162 ll = __halves2bfloat162(__float2bfloat16(r0), __float2bfloat16(r1));
    h = *reinterpret_cast<uint32_t*>(&hh);
    l = *reinterpret_cast<uint32_t*>(&ll);
}
__device__ __forceinline__ void ldsm4(uint32_t& r0, uint32_t& r1, uint32_t& r2, uint32_t& r3, uint32_t addr) {
    asm volatile("ldmatrix.sync.aligned.m8n8.x4.shared.b16 {%0,%1,%2,%3}, [%4];"
        : "=r"(r0), "=r"(r1), "=r"(r2), "=r"(r3) : "r"(addr));
}
__device__ __forceinline__ void mma16816(float* c, uint32_t a0, uint32_t a1, uint32_t a2, uint32_t a3,
                                         uint32_t b0, uint32_t b1) {
    asm volatile("mma.sync.aligned.m16n8k16.row.col.f32.bf16.bf16.f32 "
        "{%0,%1,%2,%3}, {%4,%5,%6,%7}, {%8,%9}, {%0,%1,%2,%3};"
        : "+f"(c[0]), "+f"(c[1]), "+f"(c[2]), "+f"(c[3])
        : "r"(a0), "r"(a1), "r"(a2), "r"(a3), "r"(b0), "r"(b1));
}

/* ============ init ============ */
__global__ void init_kernel() {
    int t = blockIdx.x * 256 + threadIdx.x;
    if (t < 4096) g_hist[t] = 0u;
    if (t < B_) g_rowmax[t] = 0u;
    if (t == 0) g_ncand = 0;
}

/* ============ LayerNorm(query) + q2 ============ */
__global__ void ln_kernel(const float* __restrict__ q, const float* __restrict__ gamma,
                          const float* __restrict__ beta) {
    int b = blockIdx.x, t = threadIdx.x;
    __shared__ float red[8];
    __shared__ float bc;
    float x = q[b*D_ + t];
    float s = x;
    #pragma unroll
    for (int o = 16; o; o >>= 1) s += __shfl_xor_sync(~0u, s, o);
    if ((t & 31) == 0) red[t >> 5] = s;
    __syncthreads();
    if (t == 0) { float v = 0.f; for (int i = 0; i < 8; i++) v += red[i]; bc = v * (1.0f/D_); }
    __syncthreads();
    float mu = bc, d = x - mu;
    __syncthreads();
    s = d * d;
    #pragma unroll
    for (int o = 16; o; o >>= 1) s += __shfl_xor_sync(~0u, s, o);
    if ((t & 31) == 0) red[t >> 5] = s;
    __syncthreads();
    if (t == 0) { float v = 0.f; for (int i = 0; i < 8; i++) v += red[i]; bc = v * (1.0f/D_); }
    __syncthreads();
    float qn = d * rsqrtf(bc + 1e-5f) * gamma[t] + beta[t];
    g_qn[b*D_ + t] = qn;
    __syncthreads();
    s = qn * qn;
    #pragma unroll
    for (int o = 16; o; o >>= 1) s += __shfl_xor_sync(~0u, s, o);
    if ((t & 31) == 0) red[t >> 5] = s;
    __syncthreads();
    if (t == 0) { float v = 0.f; for (int i = 0; i < 8; i++) v += red[i]; g_q2[b] = v; }
}

/* ============ k2 ============ */
__global__ void k2_kernel(const float* __restrict__ keys) {
    int row = blockIdx.x * 8 + (threadIdx.x >> 5);
    int lane = threadIdx.x & 31;
    const float4* K4 = (const float4*)keys;
    float s = 0.f;
    #pragma unroll
    for (int c = lane; c < 64; c += 32) {
        float4 v = K4[(size_t)row*64 + c];
        s += v.x*v.x + v.y*v.y + v.z*v.z + v.w*v.w;
    }
    #pragma unroll
    for (int o = 16; o; o >>= 1) s += __shfl_xor_sync(~0u, s, o);
    if (lane == 0) g_k2[row] = s;
}

/* ============ convK: keys -> bf16 hi/lo [slot][d] ============ */
__global__ void convK_kernel(const float* __restrict__ keys) {
    int tile = blockIdx.x;             /* 1024 tiles of 64 slots */
    int slot0 = tile * 64;
    for (int idx = threadIdx.x; idx < 64*128; idx += 256) {
        int row = idx >> 7, wc = idx & 127;       /* d = 2wc, 2wc+1 */
        const float* src = keys + (size_t)(slot0 + row)*256 + 2*wc;
        uint32_t h, l; split2(src[0], src[1], h, l);
        size_t off = (size_t)(slot0 + row)*256 + 2*wc;   /* half offset */
        *(uint32_t*)(g_Kh + off) = h;
        *(uint32_t*)(g_Kl + off) = l;
    }
}

/* ============ convV: values -> per-tile transposed bf16 hi/lo [v256][slot64] ============ */
__global__ void convV_kernel(const float* __restrict__ values) {
    extern __shared__ float sv[];      /* 64 x 257 floats */
    int tile = blockIdx.x;
    int slot0 = tile * 64;
    for (int idx = threadIdx.x; idx < 64*256; idx += 256) {
        int sl = idx >> 8, v = idx & 255;
        sv[sl*257 + v] = values[(size_t)(slot0 + sl)*256 + v];
    }
    __syncthreads();
    size_t tb = (size_t)tile * 16384;  /* halves per tile: 256*64 */
    for (int idx = threadIdx.x; idx < 256*32; idx += 256) {
        int v = idx >> 5, wc = idx & 31;          /* slots 2wc, 2wc+1 */
        uint32_t h, l; split2(sv[(2*wc)*257 + v], sv[(2*wc+1)*257 + v], h, l);
        size_t off = tb + (size_t)v*64 + 2*wc;
        *(uint32_t*)(g_Vth + off) = h;
        *(uint32_t*)(g_Vtl + off) = l;
    }
}

/* ============ GEMM1: S = -max(q2+k2-2 Q.K^T, 0), rowmax ============ */
/* smem: Qh[128*264] Ql Kh[64*264] Kl halves + q2s[128] k2s[64] floats */
#define G1_QH 0
#define G1_QL (128*264)
#define G1_KH (2*128*264)
#define G1_KL (2*128*264 + 64*264)
#define G1_HALVES (2*128*264 + 2*64*264)
#define G1_SMEM (G1_HALVES*2 + 128*4 + 64*4)

__global__ void __launch_bounds__(256)
gemm1_kernel() {
    extern __shared__ unsigned short sh[];
    float* q2s = (float*)(sh + G1_HALVES);
    float* k2s = q2s + 128;
    const int tid = threadIdx.x;
    const int w = tid >> 5, l = tid & 31;
    const int qb = blockIdx.x;   /* 0..7  (m-range 128) */
    const int sb = blockIdx.y;   /* 0..63 (1024 slots)  */
    const uint32_t smb = smem_u32(sh);

    /* stage Q hi/lo (once) */
    for (int idx = tid; idx < 128*128; idx += 256) {
        int row = idx >> 7, wc = idx & 127;
        const float* src = g_qn + (size_t)(qb*128 + row)*256 + 2*wc;
        uint32_t h, lo; split2(src[0], src[1], h, lo);
        *(uint32_t*)(sh + G1_QH + row*264 + 2*wc) = h;
        *(uint32_t*)(sh + G1_QL + row*264 + 2*wc) = lo;
    }
    if (tid < 128) q2s[tid] = g_q2[qb*128 + tid];

    const int g = l >> 2, tg = l & 3;
    const int m0 = 16*w;

    for (int t = 0; t < 16; t++) {
        int slot0 = sb*1024 + t*64;
        __syncthreads();   /* prior tile's reads done */
        /* stage K tile hi/lo: 2048 uint4 each (rows of 256 halves = 32 uint4) */
        {
            const uint4* srcH = (const uint4*)(g_Kh + (size_t)slot0*256);
            const uint4* srcL = (const uint4*)(g_Kl + (size_t)slot0*256);
            for (int i = tid; i < 2048; i += 256) {
                int row = i >> 5, c = i & 31;
                *(uint4*)(sh + G1_KH + row*264 + c*8) = srcH[i];
                *(uint4*)(sh + G1_KL + row*264 + c*8) = srcL[i];
            }
        }
        if (tid < 64) k2s[tid] = g_k2[slot0 + tid];
        __syncthreads();

        float acc[8][4];
        #pragma unroll
        for (int n = 0; n < 8; n++) { acc[n][0]=0.f; acc[n][1]=0.f; acc[n][2]=0.f; acc[n][3]=0.f; }

        #pragma unroll
        for (int ks = 0; ks < 16; ks++) {
            uint32_t ah0,ah1,ah2,ah3, al0,al1,al2,al3;
            {
                int row = m0 + (l & 7) + ((l >> 3) & 1)*8;
                int col = ks*16 + (l >> 4)*8;
                ldsm4(ah0,ah1,ah2,ah3, smb + (G1_QH + row*264 + col)*2);
                ldsm4(al0,al1,al2,al3, smb + (G1_QL + row*264 + col)*2);
            }
            #pragma unroll
            for (int nt2 = 0; nt2 < 4; nt2++) {
                uint32_t bh0,bh1,bh2,bh3, bl0,bl1,bl2,bl3;
                int n = nt2*16 + (l & 7) + (l >> 4)*8;
                int col = ks*16 + ((l >> 3) & 1)*8;
                ldsm4(bh0,bh1,bh2,bh3, smb + (G1_KH + n*264 + col)*2);
                ldsm4(bl0,bl1,bl2,bl3, smb + (G1_KL + n*264 + col)*2);
                mma16816(acc[nt2*2],   ah0,ah1,ah2,ah3, bh0,bh1);
                mma16816(acc[nt2*2],   ah0,ah1,ah2,ah3, bl0,bl1);
                mma16816(acc[nt2*2],   al0,al1,al2,al3, bh0,bh1);
                mma16816(acc[nt2*2+1], ah0,ah1,ah2,ah3, bh2,bh3);
                mma16816(acc[nt2*2+1], ah0,ah1,ah2,ah3, bl2,bl3);
                mma16816(acc[nt2*2+1], al0,al1,al2,al3, bh2,bh3);
            }
        }

        /* epilogue: logits + rowmax + store */
        int r0 = m0 + g, r1 = r0 + 8;
        float q20 = q2s[r0], q21 = q2s[r1];
        float mx0 = -1e30f, mx1 = -1e30f;
        float* Sbase = g_S + ((size_t)(qb*1024 + sb*16 + t)*128)*64;
        #pragma unroll
        for (int nt = 0; nt < 8; nt++) {
            int n = nt*8 + 2*tg;
            float k20 = k2s[n], k21 = k2s[n+1];
            float v00 = -fmaxf(q20 + k20 - 2.f*acc[nt][0], 0.f);
            float v01 = -fmaxf(q20 + k21 - 2.f*acc[nt][1], 0.f);
            float v10 = -fmaxf(q21 + k20 - 2.f*acc[nt][2], 0.f);
            float v11 = -fmaxf(q21 + k21 - 2.f*acc[nt][3], 0.f);
            mx0 = fmaxf(mx0, fmaxf(v00, v01));
            mx1 = fmaxf(mx1, fmaxf(v10, v11));
            *(float2*)(Sbase + (size_t)r0*64 + n) = make_float2(v00, v01);
            *(float2*)(Sbase + (size_t)r1*64 + n) = make_float2(v10, v11);
        }
        mx0 = fmaxf(mx0, __shfl_xor_sync(~0u, mx0, 1));
        mx0 = fmaxf(mx0, __shfl_xor_sync(~0u, mx0, 2));
        mx1 = fmaxf(mx1, __shfl_xor_sync(~0u, mx1, 1));
        mx1 = fmaxf(mx1, __shfl_xor_sync(~0u, mx1, 2));
        if (tg == 0) {
            atomicMax(&g_rowmax[qb*128 + r0], fkey(mx0));
            atomicMax(&g_rowmax[qb*128 + r1], fkey(mx1));
        }
    }
}

/* ============ GEMM2: O_part = exp(S - m) @ V  (M=64, N=256, split-K) ============ */
/* smem halves: Vh[256*72] Vl Ph[64*72] Pl */
#define G2_VH 0
#define G2_VL (256*72)
#define G2_PH (2*256*72)
#define G2_PL (2*256*72 + 64*72)
#define G2_HALVES (2*256*72 + 2*64*72)
#define G2_SMEM (G2_HALVES*2)

__global__ void __launch_bounds__(256)
gemm2_kernel() {
    extern __shared__ unsigned short sh[];
    const int tid = threadIdx.x;
    const int w = tid >> 5, l = tid & 31;
    const int qb2 = blockIdx.x;  /* 0..15 (m-range 64) */
    const int sp = blockIdx.y;   /* 0..31 (2048 slots) */
    const int qb = qb2 >> 1, rowbase = (qb2 & 1)*64;
    const uint32_t smb = smem_u32(sh);

    const int pr = tid >> 2, pc0 = (tid & 3)*16;      /* P staging: row, col base */
    const float Mrow = unfkey(g_rowmax[qb2*64 + pr]);
    float lsum = 0.f;

    const int mt = w >> 1, nh = w & 1;                 /* warp: m-subtile, n-half */
    const int g = l >> 2, tg = l & 3;

    float acc[16][4];
    #pragma unroll
    for (int n = 0; n < 16; n++) { acc[n][0]=0.f; acc[n][1]=0.f; acc[n][2]=0.f; acc[n][3]=0.f; }

    for (int kt = 0; kt < 32; kt++) {
        int tt = sp*32 + kt;
        __syncthreads();
        /* stage V tile hi/lo: 2048 uint4 (rows of 64 halves = 8 uint4)  [FIXED] */
        {
            const uint4* srcH = (const uint4*)(g_Vth + (size_t)tt*16384);
            const uint4* srcL = (const uint4*)(g_Vtl + (size_t)tt*16384);
            for (int i = tid; i < 2048; i += 256) {
                int row = i >> 3, c = i & 7;
                *(uint4*)(sh + G2_VH + row*72 + c*8) = srcH[i];
                *(uint4*)(sh + G2_VL + row*72 + c*8) = srcL[i];
            }
        }
        /* stage P: exp(S - M) split hi/lo */
        {
            const float4* srow = (const float4*)(g_S + ((size_t)(qb*1024 + tt)*128 + rowbase + pr)*64 + pc0);
            #pragma unroll
            for (int j = 0; j < 4; j++) {
                float4 sv = srow[j];
                float p0 = __expf(sv.x - Mrow), p1 = __expf(sv.y - Mrow);
                float p2 = __expf(sv.z - Mrow), p3 = __expf(sv.w - Mrow);
                lsum += p0 + p1 + p2 + p3;
                uint32_t h0, l0, h1, l1;
                split2(p0, p1, h0, l0);
                split2(p2, p3, h1, l1);
                *(uint32_t*)(sh + G2_PH + pr*72 + pc0 + 4*j)     = h0;
                *(uint32_t*)(sh + G2_PH + pr*72 + pc0 + 4*j + 2) = h1;
                *(uint32_t*)(sh + G2_PL + pr*72 + pc0 + 4*j)     = l0;
                *(uint32_t*)(sh + G2_PL + pr*72 + pc0 + 4*j + 2) = l1;
            }
        }
        __syncthreads();

        #pragma unroll
        for (int ks = 0; ks < 4; ks++) {
            uint32_t ah0,ah1,ah2,ah3, al0,al1,al2,al3;
            {
                int row = mt*16 + (l & 7) + ((l >> 3) & 1)*8;
                int col = ks*16 + (l >> 4)*8;
                ldsm4(ah0,ah1,ah2,ah3, smb + (G2_PH + row*72 + col)*2);
                ldsm4(al0,al1,al2,al3, smb + (G2_PL + row*72 + col)*2);
            }
            #pragma unroll
            for (int nt2 = 0; nt2 < 8; nt2++) {
                uint32_t bh0,bh1,bh2,bh3, bl0,bl1,bl2,bl3;
                int n = nh*128 + nt2*16 + (l & 7) + (l >> 4)*8;
                int col = ks*16 + ((l >> 3) & 1)*8;
                ldsm4(bh0,bh1,bh2,bh3, smb + (G2_VH + n*72 + col)*2);
                ldsm4(bl0,bl1,bl2,bl3, smb + (G2_VL + n*72 + col)*2);
                mma16816(acc[nt2*2],   ah0,ah1,ah2,ah3, bh0,bh1);
                mma16816(acc[nt2*2],   ah0,ah1,ah2,ah3, bl0,bl1);
                mma16816(acc[nt2*2],   al0,al1,al2,al3, bh0,bh1);
                mma16816(acc[nt2*2+1], ah0,ah1,ah2,ah3, bh2,bh3);
                mma16816(acc[nt2*2+1], ah0,ah1,ah2,ah3, bl2,bl3);
                mma16816(acc[nt2*2+1], al0,al1,al2,al3, bh2,bh3);
            }
        }
    }

    /* epilogue: O partials + l partials */
    {
        int mg0 = qb2*64 + mt*16 + g, mg1 = mg0 + 8;
        #pragma unroll
        for (int nt = 0; nt < 16; nt++) {
            int n = nh*128 + nt*8 + 2*tg;
            *(float2*)(g_Opart + ((size_t)mg0*NSPLIT + sp)*256 + n) = make_float2(acc[nt][0], acc[nt][1]);
            *(float2*)(g_Opart + ((size_t)mg1*NSPLIT + sp)*256 + n) = make_float2(acc[nt][2], acc[nt][3]);
        }
    }
    lsum += __shfl_xor_sync(~0u, lsum, 1);
    lsum += __shfl_xor_sync(~0u, lsum, 2);
    if ((tid & 3) == 0) g_lpart[(qb2*64 + pr)*NSPLIT + sp] = lsum;
}

/* ============ combine: retrieved + surprise ============ */
__global__ void combine_kernel(const float* __restrict__ vt, float* __restrict__ out) {
    int b = blockIdx.x, t = threadIdx.x;
    float L = 0.f;
    #pragma unroll
    for (int i = 0; i < NSPLIT; i++) L += g_lpart[b*NSPLIT + i];
    float acc = 0.f;
    #pragma unroll
    for (int i = 0; i < NSPLIT; i++)
        acc += g_Opart[((size_t)b*NSPLIT + i)*256 + t];
    float rv = acc / L;
    out[OFF_RETR + (size_t)b*V_ + t] = rv;
    float e = rv - vt[(size_t)b*V_ + t];
    float s = e * e;
    __shared__ float red[8];
    #pragma unroll
    for (int o = 16; o; o >>= 1) s += __shfl_xor_sync(~0u, s, o);
    if ((t & 31) == 0) red[t >> 5] = s;
    __syncthreads();
    if (t == 0) {
        float v = 0.f;
        for (int i = 0; i < 8; i++) v += red[i];
        float sur = v * (1.0f/V_);
        out[OFF_SUR + b] = sur;
        g_surprise[b] = sur;
    }
}

/* ============ mean(surprise) ============ */
__global__ void mean_kernel() {
    int t = threadIdx.x;
    __shared__ float red[8];
    float s = 0.f;
    for (int i = t; i < B_; i += 256) s += g_surprise[i];
    #pragma unroll
    for (int o = 16; o; o >>= 1) s += __shfl_xor_sync(~0u, s, o);
    if ((t & 31) == 0) red[t >> 5] = s;
    __syncthreads();
    if (t == 0) {
        float v = 0.f;
        for (int i = 0; i < 8; i++) v += red[i];
        g_smean = v * (1.0f/B_);
    }
}

/* ============ top-k (value-desc, index-stable) ============ */
__global__ void hist_kernel(const float* __restrict__ age) {
    int i = blockIdx.x * 256 + threadIdx.x;
    atomicAdd(&g_hist[fkey(age[i]) >> 20], 1u);
}
__global__ void thresh_kernel() {
    int cum = 0, T = 0;
    for (int i = 4095; i >= 0; i--) { cum += (int)g_hist[i]; if (cum >= NREP) { T = i; break; } }
    g_binT = T;
}
__global__ void cand_kernel(const float* __restrict__ age) {
    int i = blockIdx.x * 256 + threadIdx.x;
    unsigned int u = fkey(age[i]);
    if ((int)(u >> 20) >= g_binT) {
        int pos = atomicAdd(&g_ncand, 1);
        g_candkey[pos] = ((unsigned long long)u << 32) | (unsigned int)(~(unsigned int)i);
        g_candidx[pos] = i;
    }
}
__global__ void rank_kernel() {
    int n = g_ncand;
    __shared__ int sr[8];
    for (int c = blockIdx.x; c < n; c += gridDim.x) {
        unsigned long long kk = g_candkey[c];
        int cnt = 0;
        for (int j = threadIdx.x; j < n; j += 256) cnt += (g_candkey[j] > kk) ? 1 : 0;
        #pragma unroll
        for (int o = 16; o; o >>= 1) cnt += __shfl_xor_sync(~0u, cnt, o);
        if ((threadIdx.x & 31) == 0) sr[threadIdx.x >> 5] = cnt;
        __syncthreads();
        if (threadIdx.x == 0) {
            int tot = 0;
            for (int i = 0; i < 8; i++) tot += sr[i];
            if (tot < NREP) g_sel[tot] = g_candidx[c];
        }
        __syncthreads();
    }
}

/* ============ bulk copy ============ */
__global__ void copy_kernel(const float* __restrict__ keys, const float* __restrict__ values,
                            const float* __restrict__ age, float* __restrict__ out) {
    size_t gtid = (size_t)blockIdx.x * blockDim.x + threadIdx.x;
    size_t gstr = (size_t)gridDim.x * blockDim.x;
    const float4* K4 = (const float4*)keys;
    const float4* V4 = (const float4*)values;
    float4* oK = (float4*)(out + OFF_KEYS);
    float4* oV = (float4*)(out + OFF_VALS);
    const size_t n4 = (size_t)S_ * D_ / 4;
    for (size_t i = gtid; i < 2 * n4; i += gstr) {
        if (i < n4) oK[i] = K4[i];
        else        oV[i - n4] = V4[i - n4];
    }
    for (size_t i = gtid; i < S_; i += gstr) out[OFF_AGE + i] = age[i] + 1.0f;
}

/* ============ gated EMA scatter ============ */
__global__ void scatter_kernel(const float* __restrict__ keys, const float* __restrict__ values,
                               const float* __restrict__ vt, float* __restrict__ out) {
    int b = blockIdx.x, t = threadIdx.x;
    int slot = g_sel[b];
    float w = 1.0f / (1.0f + __expf(-(g_surprise[b] - g_smean)));
    float decay = 0.99f * (1.0f - w);
    float om = 1.0f - decay;
    out[OFF_KEYS + (size_t)slot*D_ + t] = decay * keys[(size_t)slot*D_ + t] + om * g_qn[(size_t)b*D_ + t];
    out[OFF_VALS + (size_t)slot*V_ + t] = decay * values[(size_t)slot*V_ + t] + om * vt[(size_t)b*V_ + t];
    if (t == 0) out[OFF_AGE + slot] = 1.0f;
}

/* ============ launch ============ */
extern "C" void kernel_launch(void* const* d_in, const int* in_sizes, int n_in,
                              void* d_out, int out_size) {
    const float* query  = (const float*)d_in[0];
    const float* vt     = (const float*)d_in[1];
    const float* keys   = (const float*)d_in[2];
    const float* values = (const float*)d_in[3];
    const float* age    = (const float*)d_in[4];
    const float* gamma  = (const float*)d_in[5];
    const float* beta   = (const float*)d_in[6];
    float* out = (float*)d_out;

    cudaFuncSetAttribute(gemm1_kernel, cudaFuncAttributeMaxDynamicSharedMemorySize, G1_SMEM);
    cudaFuncSetAttribute(gemm2_kernel, cudaFuncAttributeMaxDynamicSharedMemorySize, G2_SMEM);
    cudaFuncSetAttribute(convV_kernel, cudaFuncAttributeMaxDynamicSharedMemorySize, 64*257*4);

    init_kernel<<<16, 256>>>();
    ln_kernel<<<B_, 256>>>(query, gamma, beta);
    k2_kernel<<<S_/8, 256>>>(keys);
    convK_kernel<<<1024, 256>>>(keys);
    convV_kernel<<<1024, 256, 64*257*4>>>(values);
    gemm1_kernel<<<dim3(8, 64), 256, G1_SMEM>>>();
    gemm2_kernel<<<dim3(16, 32), 256, G2_SMEM>>>();
    combine_kernel<<<B_, 256>>>(vt, out);
    mean_kernel<<<1, 256>>>();
    hist_kernel<<<S_/256, 256>>>(age);
    thresh_kernel<<<1, 1>>>();
    cand_kernel<<<S_/256, 256>>>(age);
    rank_kernel<<<256, 256>>>();
    copy_kernel<<<1024, 256>>>(keys, values, age, out);
    scatter_kernel<<<B_, 256>>>(keys, values, vt, out);
}